// round 16
// baseline (speedup 1.0000x reference)
#include <cuda_runtime.h>
#include <cuda_fp16.h>
#include <cstdint>

namespace {
constexpr int B_  = 8;
constexpr int N_  = 1024;
constexpr int F_  = 1024;
constexpr int H_  = 8;
constexpr int HD_ = 128;
constexpr float SCALE_   = 0.08838834764831845f;  // 1/sqrt(128)
constexpr float NEGBIG_  = -60000.f;              // fp16-safe mask value

constexpr int BM = 128, BN = 128, BK = 64;        // BK in fp16 elements (128 B/row)
constexpr int OP_BYTES    = BM * 128;             // 16 KB per operand/stage
constexpr int STAGE_BYTES = 2 * OP_BYTES;         // 32 KB
constexpr int SMEM_BYTES  = 2 * STAGE_BYTES;      // 64 KB (2 stages)
}

// ------------------------- scratch (device globals) -------------------------
__device__ __half g_objH  [8u * 1024u * 1024u];
__device__ __half g_crossH[8u * 1024u * 1024u];
__device__ __half g_WqH [1024u * 1024u];
__device__ __half g_WkH [1024u * 1024u];
__device__ __half g_WoH [1024u * 1024u];
__device__ __half g_WvTH[1024u * 1024u];          // Wv transposed: [j][f]
__device__ __half g_WvpH[1024u * 1024u];          // Wo_flat @ Wv
__device__ float  g_bvp [1024u];
__device__ __half g_QH  [8u * 1024u * 1024u];     // [B,N,F]
__device__ __half g_KH  [8u * 1024u * 1024u];     // [B,N,F]
__device__ __half g_VpTH[8u * 1024u * 1024u];     // [F][B*N] (transposed Vp)
__device__ __half g_AH  [67108864ull];            // [B*H,N,N] fp16 raw scores -> probs

// ------------------------------- helpers ------------------------------------
__device__ __forceinline__ void cp16s(uint32_t saddr, const void* g) {
    asm volatile("cp.async.cg.shared.global [%0], [%1], 16;\n" :: "r"(saddr), "l"(g));
}

__device__ __forceinline__ void ldsm4(uint32_t& r0, uint32_t& r1, uint32_t& r2,
                                      uint32_t& r3, uint32_t saddr) {
    asm volatile("ldmatrix.sync.aligned.m8n8.x4.shared.b16 {%0,%1,%2,%3}, [%4];"
                 : "=r"(r0), "=r"(r1), "=r"(r2), "=r"(r3) : "r"(saddr));
}

__device__ __forceinline__ void mma_f16(float* d, const uint32_t* a, const uint32_t* b) {
    asm volatile(
        "mma.sync.aligned.m16n8k16.row.col.f32.f16.f16.f32 "
        "{%0,%1,%2,%3},{%4,%5,%6,%7},{%8,%9},{%0,%1,%2,%3};\n"
        : "+f"(d[0]), "+f"(d[1]), "+f"(d[2]), "+f"(d[3])
        : "r"(a[0]), "r"(a[1]), "r"(a[2]), "r"(a[3]), "r"(b[0]), "r"(b[1]));
}

// forced (non-hoistable) 128-bit global load — used for multi-pass re-reads
__device__ __forceinline__ uint4 ldg128v(const void* p) {
    uint4 d;
    asm volatile("ld.global.v4.u32 {%0,%1,%2,%3}, [%4];"
                 : "=r"(d.x), "=r"(d.y), "=r"(d.z), "=r"(d.w) : "l"(p));
    return d;
}

// --------------------------- fused pre-pass ----------------------------------
__device__ __forceinline__ void to_half_body(const float* __restrict__ in,
                                             __half* __restrict__ out, int vb) {
    size_t i = (size_t)(vb * 256 + threadIdx.x) * 4;
    float4 v = *(const float4*)(in + i);
    *(__half2*)(out + i)     = __floats2half2_rn(v.x, v.y);
    *(__half2*)(out + i + 2) = __floats2half2_rn(v.z, v.w);
}

__global__ void __launch_bounds__(256) prep_kernel(
    const float* __restrict__ obj,  const float* __restrict__ cross,
    const float* __restrict__ Wq,   const float* __restrict__ Wk,
    const float* __restrict__ Wo,   const float* __restrict__ Wv,
    const float* __restrict__ bv)
{
    const int bx = blockIdx.x;
    if (bx < 8192)       { to_half_body(obj,   g_objH,   bx);         return; }
    if (bx < 16384)      { to_half_body(cross, g_crossH, bx - 8192);  return; }
    if (bx < 17408)      { to_half_body(Wq,    g_WqH,    bx - 16384); return; }
    if (bx < 18432)      { to_half_body(Wk,    g_WkH,    bx - 17408); return; }
    if (bx < 19456)      { to_half_body(Wo,    g_WoH,    bx - 18432); return; }
    if (bx < 20480) {
        // transpose+convert Wv -> g_WvTH (32x32 tile per block)
        __shared__ float t[32][33];
        const int idx = bx - 19456;
        const int bxt = (idx & 31) * 32, byt = (idx >> 5) * 32;
        const int x = threadIdx.x & 31, y0 = threadIdx.x >> 5;   // 32 x 8
        #pragma unroll
        for (int yy = 0; yy < 32; yy += 8)
            t[y0 + yy][x] = Wv[(size_t)(byt + y0 + yy) * 1024 + bxt + x];
        __syncthreads();
        #pragma unroll
        for (int yy = 0; yy < 32; yy += 8)
            g_WvTH[(size_t)(bxt + y0 + yy) * 1024 + byt + x] = __float2half_rn(t[x][y0 + yy]);
        return;
    }
    {
        // fold_bias: bvp[o] = sum_f Wo[o,f] * bv[f]
        const int o = bx - 20480;
        float s = 0.f;
        for (int f = threadIdx.x; f < F_; f += 256)
            s += Wo[(size_t)o * F_ + f] * bv[f];
        __shared__ float red[8];
        #pragma unroll
        for (int off = 16; off; off >>= 1) s += __shfl_xor_sync(0xffffffffu, s, off);
        if ((threadIdx.x & 31) == 0) red[threadIdx.x >> 5] = s;
        __syncthreads();
        if (threadIdx.x == 0) {
            float t2 = 0.f;
            #pragma unroll
            for (int i = 0; i < 8; i++) t2 += red[i];
            g_bvp[o] = t2;
        }
    }
}

// ---------------------- FP16 tensor-core NT GEMM body -----------------------
// Smem tiles: 128 rows x 128B (64 halves), SW128 swizzle:
//   element (row, k) at byte row*128 + (((k>>3) ^ (row&7)) << 4) + (k&7)*2
// Fragments via ldmatrix.x4.b16; mma.m16n8k16, fp32 accumulate.
//
// MODE 0: fold      g_WvpH = WoH @ WvTH^T
// MODE 1: Q         g_QH   = objH @ WqH^T + bq
// MODE 2: K         g_KH   = crossH @ WkH^T + bk
// MODE 3: Vp        g_VpTH = (crossH @ WvpH^T + bvp)^T    (transposed store)
// MODE 4: scores    g_AH[z] = (Qh @ Kh^T) * SCALE  (fp16 out, write-only epi)
// MODE 5: AV        out_h  = AH_z @ VpTH_h^T + bo_h  (fp32 out)
template<int MODE>
__device__ __forceinline__ void gemm_body(
    int bxi, int byi, int bzi, __half* smh,
    const float* __restrict__ bias, float* __restrict__ outp)
{
    const uint32_t smemU = (uint32_t)__cvta_generic_to_shared(smh);

    const int tid  = threadIdx.x;
    const int warp = tid >> 5, lane = tid & 31;
    const int wm0 = (warp & 1) * 64, wn0 = (warp >> 1) * 64;
    const int r = lane >> 2, c = lane & 3;
    const int ro = byi * BM, co = bxi * BN;

    int zb = 0, zh = 0;
    if constexpr (MODE >= 4) { zb = bzi >> 3; zh = bzi & 7; }

    const __half* Ap; const __half* Bp;
    __half* CpH = nullptr; float* CpF = nullptr;
    int lda, ldb, ldc, KD;
    if constexpr (MODE == 0) { Ap = g_WoH;   Bp = g_WvTH; CpH = g_WvpH; lda = ldb = ldc = F_; KD = F_; }
    if constexpr (MODE == 1) { Ap = g_objH;  Bp = g_WqH;  CpH = g_QH;   lda = ldb = ldc = F_; KD = F_; }
    if constexpr (MODE == 2) { Ap = g_crossH;Bp = g_WkH;  CpH = g_KH;   lda = ldb = ldc = F_; KD = F_; }
    if constexpr (MODE == 3) { Ap = g_crossH;Bp = g_WvpH; CpH = g_VpTH; lda = ldb = F_; ldc = 8192; KD = F_; }
    if constexpr (MODE == 4) {
        Ap = g_QH + (size_t)zb * N_ * F_ + zh * HD_; lda = F_;
        Bp = g_KH + (size_t)zb * N_ * F_ + zh * HD_; ldb = F_;
        CpH = g_AH + (size_t)bzi * N_ * N_;          ldc = N_; KD = HD_;
    }
    if constexpr (MODE == 5) {
        Ap = g_AH + (size_t)bzi * N_ * N_;                   lda = N_;
        Bp = g_VpTH + (size_t)zh * HD_ * 8192 + zb * N_;     ldb = 8192;
        CpF = outp + (size_t)zb * N_ * F_ + zh * HD_;        ldc = F_; KD = F_;
    }

    float acc[4][8][4];
    #pragma unroll
    for (int i = 0; i < 4; i++)
        #pragma unroll
        for (int j = 0; j < 8; j++)
            #pragma unroll
            for (int k = 0; k < 4; k++) acc[i][j][k] = 0.f;

    // ---- cp.async geometry: 8 chunks of 16B per 128B row ----
    const int ldRow0 = tid >> 3;
    const int ldCh   = tid & 7;
    const uint32_t ldSwz = (uint32_t)((ldCh ^ (ldRow0 & 7)) << 4);

    auto loadTile = [&](int kt, int s) {
        const int k0 = kt * BK;
        const uint32_t aS = smemU + (uint32_t)(s * STAGE_BYTES);
        const uint32_t bS = aS + (uint32_t)OP_BYTES;
        #pragma unroll
        for (int i = 0; i < 8; i++) {
            const int row = ldRow0 + 16 * i;
            cp16s(aS + (uint32_t)row * 128u + ldSwz,
                  Ap + (size_t)(ro + row) * lda + k0 + ldCh * 8);
            cp16s(bS + (uint32_t)row * 128u + ldSwz,
                  Bp + (size_t)(co + row) * ldb + k0 + ldCh * 8);
        }
    };

    // ---- ldmatrix geometry (16B chunk = 8 halves) ----
    const int aRowT = lane & 15;
    const int aSel  = lane >> 4;
    const int aXr   = aRowT & 7;
    const int bRowT = (lane & 7) + ((lane >> 4) << 3);
    const int bSel  = (lane >> 3) & 1;
    const int bXr   = bRowT & 7;
    uint32_t aRowOff[4], bRowOff[4];
    #pragma unroll
    for (int mt = 0; mt < 4; mt++) aRowOff[mt] = (uint32_t)((wm0 + mt * 16 + aRowT) * 128);
    #pragma unroll
    for (int p = 0; p < 4; p++)   bRowOff[p]  = (uint32_t)((wn0 + p * 16 + bRowT) * 128);

    const int T = KD / BK;   // 16 (proj/fold/AV), 2 (scores)
    loadTile(0, 0);
    asm volatile("cp.async.commit_group;\n");

    for (int kt = 0; kt < T; ++kt) {
        const int s = kt & 1;
        if (kt + 1 < T) {
            loadTile(kt + 1, s ^ 1);
            asm volatile("cp.async.commit_group;\n");
            asm volatile("cp.async.wait_group 1;\n");
        } else {
            asm volatile("cp.async.wait_group 0;\n");
        }
        __syncthreads();

        const uint32_t aS = smemU + (uint32_t)(s * STAGE_BYTES);
        const uint32_t bS = aS + (uint32_t)OP_BYTES;

        #pragma unroll
        for (int j16 = 0; j16 < 4; ++j16) {          // k16 steps within k64
            const int c0 = j16 * 2;
            uint32_t a[4][4], b[8][2];
            const uint32_t aCh = (uint32_t)(((c0 + aSel) ^ aXr) << 4);
            #pragma unroll
            for (int mt = 0; mt < 4; mt++)
                ldsm4(a[mt][0], a[mt][1], a[mt][2], a[mt][3], aS + aRowOff[mt] + aCh);
            const uint32_t bCh = (uint32_t)(((c0 + bSel) ^ bXr) << 4);
            #pragma unroll
            for (int p = 0; p < 4; p++)
                ldsm4(b[2*p][0], b[2*p][1], b[2*p+1][0], b[2*p+1][1], bS + bRowOff[p] + bCh);
            #pragma unroll
            for (int mt = 0; mt < 4; mt++)
                #pragma unroll
                for (int nt = 0; nt < 8; nt++) mma_f16(acc[mt][nt], a[mt], b[nt]);
        }
        __syncthreads();
    }

    // ------------------------------ epilogues -------------------------------
    if constexpr (MODE == 3) {
        // transposed fp16 store via smem staging (stride 136 halves = 272B)
        __half* st = smh;
        #pragma unroll
        for (int half_ = 0; half_ < 2; ++half_) {
            __syncthreads();
            #pragma unroll
            for (int mt = 0; mt < 4; mt++)
                #pragma unroll
                for (int nt = 0; nt < 8; nt++)
                    #pragma unroll
                    for (int h2 = 0; h2 < 2; h2++)
                        #pragma unroll
                        for (int j = 0; j < 2; j++) {
                            const int colL = wn0 + nt * 8 + c * 2 + j;
                            if ((colL >> 6) == half_) {
                                const int rowL = wm0 + mt * 16 + r + h2 * 8;
                                st[(colL & 63) * 136 + rowL] =
                                    __float2half_rn(acc[mt][nt][h2 * 2 + j] + g_bvp[co + colL]);
                            }
                        }
            __syncthreads();
            #pragma unroll
            for (int i = 0; i < 8; i++) {
                const int q = tid + 128 * i;            // 0..1023
                const int fr = q >> 4, m16 = q & 15;    // 64 f-rows x 16 chunks of 8 halves
                uint4 v = *(const uint4*)&st[fr * 136 + m16 * 8];
                *(uint4*)&g_VpTH[(size_t)(co + half_ * 64 + fr) * 8192 + ro + m16 * 8] = v;
            }
        }
        return;
    }

    #pragma unroll
    for (int mt = 0; mt < 4; mt++)
        #pragma unroll
        for (int nt = 0; nt < 8; nt++)
            #pragma unroll
            for (int h2 = 0; h2 < 2; h2++) {
                const int row  = ro + wm0 + mt * 16 + r + h2 * 8;
                const int colL = wn0 + nt * 8 + c * 2;
                const int col  = co + colL;
                float v0 = acc[mt][nt][h2 * 2 + 0];
                float v1 = acc[mt][nt][h2 * 2 + 1];
                if constexpr (MODE == 0) {
                    *(__half2*)&CpH[(size_t)row * ldc + col] = __floats2half2_rn(v0, v1);
                }
                if constexpr (MODE == 1 || MODE == 2) {
                    v0 += bias[col]; v1 += bias[col + 1];
                    *(__half2*)&CpH[(size_t)row * ldc + col] = __floats2half2_rn(v0, v1);
                }
                if constexpr (MODE == 4) {
                    *(__half2*)&CpH[(size_t)row * ldc + col] =
                        __floats2half2_rn(v0 * SCALE_, v1 * SCALE_);
                }
                if constexpr (MODE == 5) {
                    v0 += bias[colL]; v1 += bias[colL + 1];
                    *(float2*)&CpF[(size_t)row * ldc + col] = make_float2(v0, v1);
                }
            }
}

// --------------------------- kernel wrappers --------------------------------
template<int MODE>
__global__ void __launch_bounds__(128, 2) tgemm(
    const float* __restrict__ bias, float* __restrict__ outp)
{
    extern __shared__ __align__(16) __half smh[];
    gemm_body<MODE>(blockIdx.x, blockIdx.y, blockIdx.z, smh, bias, outp);
}

// Q (z=0), K (z=1), fold (z=2, only 8x8 tiles active) in one launch
__global__ void __launch_bounds__(128, 2) qkf_kernel(
    const float* __restrict__ bq, const float* __restrict__ bk)
{
    extern __shared__ __align__(16) __half smh[];
    if (blockIdx.z == 0) {
        gemm_body<1>(blockIdx.x, blockIdx.y, 0, smh, bq, nullptr);
    } else if (blockIdx.z == 1) {
        gemm_body<2>(blockIdx.x, blockIdx.y, 0, smh, bk, nullptr);
    } else if (blockIdx.y < 8) {
        gemm_body<0>(blockIdx.x, blockIdx.y, 0, smh, nullptr, nullptr);
    }
}

// Scores (blocks 0..4095, scheduled first) co-scheduled with VpT GEMM
// (blocks 4096..4607) — both tensor-GEMM register class, 2 CTAs/SM.
__global__ void __launch_bounds__(128, 2) scores_vpt_kernel()
{
    extern __shared__ __align__(16) __half smh[];
    const int bx = blockIdx.x;
    if (bx < 4096) {
        gemm_body<4>(bx & 7, (bx >> 3) & 7, bx >> 6, smh, nullptr, nullptr);
    } else {
        const int idx = bx - 4096;
        gemm_body<3>(idx & 7, idx >> 3, 0, smh, nullptr, nullptr);
    }
}

// Warp-per-row softmax + att_avg, 3-phase (max / sum / normalize+write) per head.
// Re-reads the row each phase via non-hoistable volatile loads -> low live regs
// (~65) at full warp-level MLP (4 outstanding 16B loads), no block barriers.
__global__ void __launch_bounds__(128, 6) softmax_attavg_kernel(
    const int* __restrict__ adj, const float* __restrict__ label,
    float* __restrict__ out_att)
{
    const int lane = threadIdx.x & 31;
    const int gw = blockIdx.x * 4 + (threadIdx.x >> 5);  // (b*N + n)
    const int b = gw >> 10, n = gw & 1023;

    // mask+label addterm, packed fp16x2 (adj>0 ? label : NEGBIG)
    __half2 addt[16];
    {
        const size_t rbase = ((size_t)(b << 10) + n) * 1024 + lane * 8;
        const int*   ar = adj   + rbase;
        const float* lr = label + rbase;
        #pragma unroll
        for (int i = 0; i < 4; i++) {
            const int4   a0 = *(const int4*)  (ar + i * 256);
            const int4   a1 = *(const int4*)  (ar + i * 256 + 4);
            const float4 l0 = *(const float4*)(lr + i * 256);
            const float4 l1 = *(const float4*)(lr + i * 256 + 4);
            addt[i*4+0] = __float22half2_rn(make_float2(a0.x > 0 ? l0.x : NEGBIG_,
                                                        a0.y > 0 ? l0.y : NEGBIG_));
            addt[i*4+1] = __float22half2_rn(make_float2(a0.z > 0 ? l0.z : NEGBIG_,
                                                        a0.w > 0 ? l0.w : NEGBIG_));
            addt[i*4+2] = __float22half2_rn(make_float2(a1.x > 0 ? l1.x : NEGBIG_,
                                                        a1.y > 0 ? l1.y : NEGBIG_));
            addt[i*4+3] = __float22half2_rn(make_float2(a1.z > 0 ? l1.z : NEGBIG_,
                                                        a1.w > 0 ? l1.w : NEGBIG_));
        }
    }

    float2 avg[16];
    #pragma unroll
    for (int i = 0; i < 16; i++) avg[i] = make_float2(0.f, 0.f);

    #pragma unroll 1
    for (int h = 0; h < H_; h++) {
        __half* ph = g_AH + (((size_t)(b * H_ + h) << 10) + n) * 1024 + lane * 8;

        // ---- phase A: row max ----
        float mx = -1e30f;
        #pragma unroll
        for (int i = 0; i < 4; i++) {
            const uint4 d = ldg128v(ph + i * 256);
            const __half2* hp = (const __half2*)&d;
            #pragma unroll
            for (int j = 0; j < 4; j++) {
                const float2 v = __half22float2(hp[j]);
                const float2 a = __half22float2(addt[i*4+j]);
                mx = fmaxf(mx, fmaxf(v.x + a.x, v.y + a.y));
            }
        }
        #pragma unroll
        for (int o = 16; o; o >>= 1) mx = fmaxf(mx, __shfl_xor_sync(0xffffffffu, mx, o));

        // ---- phase B: row sum of exp ----
        float s = 0.f;
        #pragma unroll
        for (int i = 0; i < 4; i++) {
            const uint4 d = ldg128v(ph + i * 256);
            const __half2* hp = (const __half2*)&d;
            #pragma unroll
            for (int j = 0; j < 4; j++) {
                const float2 v = __half22float2(hp[j]);
                const float2 a = __half22float2(addt[i*4+j]);
                s += __expf(v.x + a.x - mx) + __expf(v.y + a.y - mx);
            }
        }
        #pragma unroll
        for (int o = 16; o; o >>= 1) s += __shfl_xor_sync(0xffffffffu, s, o);
        const float inv = 1.0f / s;

        // ---- phase C: normalize, accumulate avg, write probs ----
        #pragma unroll
        for (int i = 0; i < 4; i++) {
            const uint4 din = ldg128v(ph + i * 256);
            const __half2* hp = (const __half2*)&din;
            uint4 dout;
            __half2* op = (__half2*)&dout;
            #pragma unroll
            for (int j = 0; j < 4; j++) {
                const float2 v = __half22float2(hp[j]);
                const float2 a = __half22float2(addt[i*4+j]);
                const float p0 = __expf(v.x + a.x - mx) * inv;
                const float p1 = __expf(v.y + a.y - mx) * inv;
                avg[i*4+j].x += p0; avg[i*4+j].y += p1;
                op[j] = __floats2half2_rn(p0, p1);
            }
            *(uint4*)(ph + i * 256) = dout;
        }
    }

    float* pa = out_att + (((size_t)b << 10) + n) * 1024 + lane * 8;
    #pragma unroll
    for (int i = 0; i < 4; i++) {
        *(float4*)(pa + i * 256) = make_float4(
            avg[i*4+0].x * 0.125f, avg[i*4+0].y * 0.125f,
            avg[i*4+1].x * 0.125f, avg[i*4+1].y * 0.125f);
        *(float4*)(pa + i * 256 + 4) = make_float4(
            avg[i*4+2].x * 0.125f, avg[i*4+2].y * 0.125f,
            avg[i*4+3].x * 0.125f, avg[i*4+3].y * 0.125f);
    }
}

// ----------------------------------------------------------------------------
extern "C" void kernel_launch(void* const* d_in, const int* in_sizes, int n_in,
                              void* d_out, int out_size) {
    const float* obj   = (const float*)d_in[0];
    const float* cross = (const float*)d_in[1];
    const int*   adj   = (const int*)  d_in[2];
    const float* label = (const float*)d_in[3];
    const float* Wq    = (const float*)d_in[4];
    const float* bq    = (const float*)d_in[5];
    const float* Wk    = (const float*)d_in[6];
    const float* bk    = (const float*)d_in[7];
    const float* Wv    = (const float*)d_in[8];
    const float* bv    = (const float*)d_in[9];
    const float* Wo    = (const float*)d_in[10];
    const float* bo    = (const float*)d_in[11];

    float* out     = (float*)d_out;
    float* out_att = out + (size_t)B_ * N_ * F_;

    cudaFuncSetAttribute(tgemm<5>, cudaFuncAttributeMaxDynamicSharedMemorySize, SMEM_BYTES);
    cudaFuncSetAttribute(qkf_kernel, cudaFuncAttributeMaxDynamicSharedMemorySize, SMEM_BYTES);
    cudaFuncSetAttribute(scores_vpt_kernel, cudaFuncAttributeMaxDynamicSharedMemorySize, SMEM_BYTES);

    // ---- fused pre-pass (to_half x5 + transpose + fold_bias) ----
    prep_kernel<<<21504, 256>>>(obj, cross, Wq, Wk, Wo, Wv, bv);

    // ---- Q + K + fold co-scheduled ----
    qkf_kernel<<<dim3(8, 64, 3), 128, SMEM_BYTES>>>(bq, bk);
    // ---- scores (write-only epi) co-scheduled with VpT GEMM ----
    scores_vpt_kernel<<<4608, 128, SMEM_BYTES>>>();
    // ---- 3-phase warp-per-row softmax(mask+label) + att_avg ----
    softmax_attavg_kernel<<<2048, 128>>>(adj, label, out_att);
    // ---- AV ----
    tgemm<5><<<dim3(1, 8, 64), 128, SMEM_BYTES>>>(bo, out);
}

// round 17
// speedup vs baseline: 1.0542x; 1.0542x over previous
#include <cuda_runtime.h>
#include <cuda_fp16.h>
#include <cstdint>

namespace {
constexpr int B_  = 8;
constexpr int N_  = 1024;
constexpr int F_  = 1024;
constexpr int H_  = 8;
constexpr int HD_ = 128;
constexpr float SCALE_   = 0.08838834764831845f;  // 1/sqrt(128)
constexpr float NEGBIG_  = -60000.f;              // fp16-safe mask value

constexpr int BM = 128, BN = 128, BK = 64;        // BK in fp16 elements (128 B/row)
constexpr int OP_BYTES    = BM * 128;             // 16 KB per operand/stage
constexpr int STAGE_BYTES = 2 * OP_BYTES;         // 32 KB
constexpr int SMEM_BYTES  = 2 * STAGE_BYTES;      // 64 KB (2 stages)
}

// ------------------------- scratch (device globals) -------------------------
__device__ __half g_objH  [8u * 1024u * 1024u];
__device__ __half g_crossH[8u * 1024u * 1024u];
__device__ __half g_WqH [1024u * 1024u];
__device__ __half g_WkH [1024u * 1024u];
__device__ __half g_WoH [1024u * 1024u];
__device__ __half g_WvTH[1024u * 1024u];          // Wv transposed: [j][f]
__device__ __half g_WvpH[1024u * 1024u];          // Wo_flat @ Wv
__device__ float  g_bvp [1024u];
__device__ __half g_QH  [8u * 1024u * 1024u];     // [B,N,F]
__device__ __half g_KH  [8u * 1024u * 1024u];     // [B,N,F]
__device__ __half g_VpTH[8u * 1024u * 1024u];     // [F][B*N] (transposed Vp)
__device__ __half g_AH  [67108864ull];            // [B*H,N,N] fp16 raw scores -> probs

// ------------------------------- helpers ------------------------------------
__device__ __forceinline__ void cp16s(uint32_t saddr, const void* g) {
    asm volatile("cp.async.cg.shared.global [%0], [%1], 16;\n" :: "r"(saddr), "l"(g));
}

__device__ __forceinline__ void ldsm4(uint32_t& r0, uint32_t& r1, uint32_t& r2,
                                      uint32_t& r3, uint32_t saddr) {
    asm volatile("ldmatrix.sync.aligned.m8n8.x4.shared.b16 {%0,%1,%2,%3}, [%4];"
                 : "=r"(r0), "=r"(r1), "=r"(r2), "=r"(r3) : "r"(saddr));
}

__device__ __forceinline__ void mma_f16(float* d, const uint32_t* a, const uint32_t* b) {
    asm volatile(
        "mma.sync.aligned.m16n8k16.row.col.f32.f16.f16.f32 "
        "{%0,%1,%2,%3},{%4,%5,%6,%7},{%8,%9},{%0,%1,%2,%3};\n"
        : "+f"(d[0]), "+f"(d[1]), "+f"(d[2]), "+f"(d[3])
        : "r"(a[0]), "r"(a[1]), "r"(a[2]), "r"(a[3]), "r"(b[0]), "r"(b[1]));
}

// --------------------------- fused pre-pass ----------------------------------
__device__ __forceinline__ void to_half_body(const float* __restrict__ in,
                                             __half* __restrict__ out, int vb) {
    size_t i = (size_t)(vb * 256 + threadIdx.x) * 4;
    float4 v = *(const float4*)(in + i);
    *(__half2*)(out + i)     = __floats2half2_rn(v.x, v.y);
    *(__half2*)(out + i + 2) = __floats2half2_rn(v.z, v.w);
}

__global__ void __launch_bounds__(256) prep_kernel(
    const float* __restrict__ obj,  const float* __restrict__ cross,
    const float* __restrict__ Wq,   const float* __restrict__ Wk,
    const float* __restrict__ Wo,   const float* __restrict__ Wv,
    const float* __restrict__ bv)
{
    const int bx = blockIdx.x;
    if (bx < 8192)       { to_half_body(obj,   g_objH,   bx);         return; }
    if (bx < 16384)      { to_half_body(cross, g_crossH, bx - 8192);  return; }
    if (bx < 17408)      { to_half_body(Wq,    g_WqH,    bx - 16384); return; }
    if (bx < 18432)      { to_half_body(Wk,    g_WkH,    bx - 17408); return; }
    if (bx < 19456)      { to_half_body(Wo,    g_WoH,    bx - 18432); return; }
    if (bx < 20480) {
        // transpose+convert Wv -> g_WvTH (32x32 tile per block)
        __shared__ float t[32][33];
        const int idx = bx - 19456;
        const int bxt = (idx & 31) * 32, byt = (idx >> 5) * 32;
        const int x = threadIdx.x & 31, y0 = threadIdx.x >> 5;   // 32 x 8
        #pragma unroll
        for (int yy = 0; yy < 32; yy += 8)
            t[y0 + yy][x] = Wv[(size_t)(byt + y0 + yy) * 1024 + bxt + x];
        __syncthreads();
        #pragma unroll
        for (int yy = 0; yy < 32; yy += 8)
            g_WvTH[(size_t)(bxt + y0 + yy) * 1024 + byt + x] = __float2half_rn(t[x][y0 + yy]);
        return;
    }
    {
        // fold_bias: bvp[o] = sum_f Wo[o,f] * bv[f]
        const int o = bx - 20480;
        float s = 0.f;
        for (int f = threadIdx.x; f < F_; f += 256)
            s += Wo[(size_t)o * F_ + f] * bv[f];
        __shared__ float red[8];
        #pragma unroll
        for (int off = 16; off; off >>= 1) s += __shfl_xor_sync(0xffffffffu, s, off);
        if ((threadIdx.x & 31) == 0) red[threadIdx.x >> 5] = s;
        __syncthreads();
        if (threadIdx.x == 0) {
            float t2 = 0.f;
            #pragma unroll
            for (int i = 0; i < 8; i++) t2 += red[i];
            g_bvp[o] = t2;
        }
    }
}

// ---------------------- FP16 tensor-core NT GEMM body -----------------------
// Smem tiles: 128 rows x 128B (64 halves), SW128 swizzle:
//   element (row, k) at byte row*128 + (((k>>3) ^ (row&7)) << 4) + (k&7)*2
// Fragments via ldmatrix.x4.b16; mma.m16n8k16, fp32 accumulate.
//
// MODE 0: fold      g_WvpH = WoH @ WvTH^T
// MODE 1: Q         g_QH   = objH @ WqH^T + bq
// MODE 2: K         g_KH   = crossH @ WkH^T + bk
// MODE 3: Vp        g_VpTH = (crossH @ WvpH^T + bvp)^T    (transposed store)
// MODE 4: scores    g_AH[z] = (Qh @ Kh^T) * SCALE  (fp16 out, write-only epi)
// MODE 5: AV        out_h  = AH_z @ VpTH_h^T + bo_h  (fp32 out)
template<int MODE>
__device__ __forceinline__ void gemm_body(
    int bxi, int byi, int bzi, __half* smh,
    const float* __restrict__ bias, float* __restrict__ outp)
{
    const uint32_t smemU = (uint32_t)__cvta_generic_to_shared(smh);

    const int tid  = threadIdx.x;
    const int warp = tid >> 5, lane = tid & 31;
    const int wm0 = (warp & 1) * 64, wn0 = (warp >> 1) * 64;
    const int r = lane >> 2, c = lane & 3;
    const int ro = byi * BM, co = bxi * BN;

    int zb = 0, zh = 0;
    if constexpr (MODE >= 4) { zb = bzi >> 3; zh = bzi & 7; }

    const __half* Ap; const __half* Bp;
    __half* CpH = nullptr; float* CpF = nullptr;
    int lda, ldb, ldc, KD;
    if constexpr (MODE == 0) { Ap = g_WoH;   Bp = g_WvTH; CpH = g_WvpH; lda = ldb = ldc = F_; KD = F_; }
    if constexpr (MODE == 1) { Ap = g_objH;  Bp = g_WqH;  CpH = g_QH;   lda = ldb = ldc = F_; KD = F_; }
    if constexpr (MODE == 2) { Ap = g_crossH;Bp = g_WkH;  CpH = g_KH;   lda = ldb = ldc = F_; KD = F_; }
    if constexpr (MODE == 3) { Ap = g_crossH;Bp = g_WvpH; CpH = g_VpTH; lda = ldb = F_; ldc = 8192; KD = F_; }
    if constexpr (MODE == 4) {
        Ap = g_QH + (size_t)zb * N_ * F_ + zh * HD_; lda = F_;
        Bp = g_KH + (size_t)zb * N_ * F_ + zh * HD_; ldb = F_;
        CpH = g_AH + (size_t)bzi * N_ * N_;          ldc = N_; KD = HD_;
    }
    if constexpr (MODE == 5) {
        Ap = g_AH + (size_t)bzi * N_ * N_;                   lda = N_;
        Bp = g_VpTH + (size_t)zh * HD_ * 8192 + zb * N_;     ldb = 8192;
        CpF = outp + (size_t)zb * N_ * F_ + zh * HD_;        ldc = F_; KD = F_;
    }

    float acc[4][8][4];
    #pragma unroll
    for (int i = 0; i < 4; i++)
        #pragma unroll
        for (int j = 0; j < 8; j++)
            #pragma unroll
            for (int k = 0; k < 4; k++) acc[i][j][k] = 0.f;

    // ---- cp.async geometry: 8 chunks of 16B per 128B row ----
    const int ldRow0 = tid >> 3;
    const int ldCh   = tid & 7;
    const uint32_t ldSwz = (uint32_t)((ldCh ^ (ldRow0 & 7)) << 4);

    auto loadTile = [&](int kt, int s) {
        const int k0 = kt * BK;
        const uint32_t aS = smemU + (uint32_t)(s * STAGE_BYTES);
        const uint32_t bS = aS + (uint32_t)OP_BYTES;
        #pragma unroll
        for (int i = 0; i < 8; i++) {
            const int row = ldRow0 + 16 * i;
            cp16s(aS + (uint32_t)row * 128u + ldSwz,
                  Ap + (size_t)(ro + row) * lda + k0 + ldCh * 8);
            cp16s(bS + (uint32_t)row * 128u + ldSwz,
                  Bp + (size_t)(co + row) * ldb + k0 + ldCh * 8);
        }
    };

    // ---- ldmatrix geometry (16B chunk = 8 halves) ----
    const int aRowT = lane & 15;
    const int aSel  = lane >> 4;
    const int aXr   = aRowT & 7;
    const int bRowT = (lane & 7) + ((lane >> 4) << 3);
    const int bSel  = (lane >> 3) & 1;
    const int bXr   = bRowT & 7;
    uint32_t aRowOff[4], bRowOff[4];
    #pragma unroll
    for (int mt = 0; mt < 4; mt++) aRowOff[mt] = (uint32_t)((wm0 + mt * 16 + aRowT) * 128);
    #pragma unroll
    for (int p = 0; p < 4; p++)   bRowOff[p]  = (uint32_t)((wn0 + p * 16 + bRowT) * 128);

    const int T = KD / BK;   // 16 (proj/fold/AV), 2 (scores)
    loadTile(0, 0);
    asm volatile("cp.async.commit_group;\n");

    for (int kt = 0; kt < T; ++kt) {
        const int s = kt & 1;
        if (kt + 1 < T) {
            loadTile(kt + 1, s ^ 1);
            asm volatile("cp.async.commit_group;\n");
            asm volatile("cp.async.wait_group 1;\n");
        } else {
            asm volatile("cp.async.wait_group 0;\n");
        }
        __syncthreads();

        const uint32_t aS = smemU + (uint32_t)(s * STAGE_BYTES);
        const uint32_t bS = aS + (uint32_t)OP_BYTES;

        #pragma unroll
        for (int j16 = 0; j16 < 4; ++j16) {          // k16 steps within k64
            const int c0 = j16 * 2;
            uint32_t a[4][4], b[8][2];
            const uint32_t aCh = (uint32_t)(((c0 + aSel) ^ aXr) << 4);
            #pragma unroll
            for (int mt = 0; mt < 4; mt++)
                ldsm4(a[mt][0], a[mt][1], a[mt][2], a[mt][3], aS + aRowOff[mt] + aCh);
            const uint32_t bCh = (uint32_t)(((c0 + bSel) ^ bXr) << 4);
            #pragma unroll
            for (int p = 0; p < 4; p++)
                ldsm4(b[2*p][0], b[2*p][1], b[2*p+1][0], b[2*p+1][1], bS + bRowOff[p] + bCh);
            #pragma unroll
            for (int mt = 0; mt < 4; mt++)
                #pragma unroll
                for (int nt = 0; nt < 8; nt++) mma_f16(acc[mt][nt], a[mt], b[nt]);
        }
        __syncthreads();
    }

    // ------------------------------ epilogues -------------------------------
    if constexpr (MODE == 3) {
        // transposed fp16 store via smem staging (stride 136 halves = 272B)
        __half* st = smh;
        #pragma unroll
        for (int half_ = 0; half_ < 2; ++half_) {
            __syncthreads();
            #pragma unroll
            for (int mt = 0; mt < 4; mt++)
                #pragma unroll
                for (int nt = 0; nt < 8; nt++)
                    #pragma unroll
                    for (int h2 = 0; h2 < 2; h2++)
                        #pragma unroll
                        for (int j = 0; j < 2; j++) {
                            const int colL = wn0 + nt * 8 + c * 2 + j;
                            if ((colL >> 6) == half_) {
                                const int rowL = wm0 + mt * 16 + r + h2 * 8;
                                st[(colL & 63) * 136 + rowL] =
                                    __float2half_rn(acc[mt][nt][h2 * 2 + j] + g_bvp[co + colL]);
                            }
                        }
            __syncthreads();
            #pragma unroll
            for (int i = 0; i < 8; i++) {
                const int q = tid + 128 * i;            // 0..1023
                const int fr = q >> 4, m16 = q & 15;    // 64 f-rows x 16 chunks of 8 halves
                uint4 v = *(const uint4*)&st[fr * 136 + m16 * 8];
                *(uint4*)&g_VpTH[(size_t)(co + half_ * 64 + fr) * 8192 + ro + m16 * 8] = v;
            }
        }
        return;
    }

    #pragma unroll
    for (int mt = 0; mt < 4; mt++)
        #pragma unroll
        for (int nt = 0; nt < 8; nt++)
            #pragma unroll
            for (int h2 = 0; h2 < 2; h2++) {
                const int row  = ro + wm0 + mt * 16 + r + h2 * 8;
                const int colL = wn0 + nt * 8 + c * 2;
                const int col  = co + colL;
                float v0 = acc[mt][nt][h2 * 2 + 0];
                float v1 = acc[mt][nt][h2 * 2 + 1];
                if constexpr (MODE == 0) {
                    *(__half2*)&CpH[(size_t)row * ldc + col] = __floats2half2_rn(v0, v1);
                }
                if constexpr (MODE == 1 || MODE == 2) {
                    v0 += bias[col]; v1 += bias[col + 1];
                    *(__half2*)&CpH[(size_t)row * ldc + col] = __floats2half2_rn(v0, v1);
                }
                if constexpr (MODE == 4) {
                    *(__half2*)&CpH[(size_t)row * ldc + col] =
                        __floats2half2_rn(v0 * SCALE_, v1 * SCALE_);
                }
                if constexpr (MODE == 5) {
                    v0 += bias[colL]; v1 += bias[colL + 1];
                    *(float2*)&CpF[(size_t)row * ldc + col] = make_float2(v0, v1);
                }
            }
}

// --------------------------- kernel wrappers --------------------------------
template<int MODE>
__global__ void __launch_bounds__(128, 2) tgemm(
    const float* __restrict__ bias, float* __restrict__ outp)
{
    extern __shared__ __align__(16) __half smh[];
    gemm_body<MODE>(blockIdx.x, blockIdx.y, blockIdx.z, smh, bias, outp);
}

// Q (z=0), K (z=1), fold (z=2, only 8x8 tiles active) in one launch
__global__ void __launch_bounds__(128, 2) qkf_kernel(
    const float* __restrict__ bq, const float* __restrict__ bk)
{
    extern __shared__ __align__(16) __half smh[];
    if (blockIdx.z == 0) {
        gemm_body<1>(blockIdx.x, blockIdx.y, 0, smh, bq, nullptr);
    } else if (blockIdx.z == 1) {
        gemm_body<2>(blockIdx.x, blockIdx.y, 0, smh, bk, nullptr);
    } else if (blockIdx.y < 8) {
        gemm_body<0>(blockIdx.x, blockIdx.y, 0, smh, nullptr, nullptr);
    }
}

// Scores (blocks 0..4095, scheduled first) co-scheduled with VpT GEMM
// (blocks 4096..4607) — both tensor-GEMM register class, 2 CTAs/SM.
__global__ void __launch_bounds__(128, 2) scores_vpt_kernel()
{
    extern __shared__ __align__(16) __half smh[];
    const int bx = blockIdx.x;
    if (bx < 4096) {
        gemm_body<4>(bx & 7, (bx >> 3) & 7, bx >> 6, smh, nullptr, nullptr);
    } else {
        const int idx = bx - 4096;
        gemm_body<3>(idx & 7, idx >> 3, 0, smh, nullptr, nullptr);
    }
}

// Warp-per-row softmax + att_avg (round-13 configuration: full row in registers,
// shfl-only reductions, high per-warp MLP — empirically the local optimum).
__global__ void __launch_bounds__(128) softmax_attavg_kernel(
    const int* __restrict__ adj, const float* __restrict__ label,
    float* __restrict__ out_att)
{
    const int lane = threadIdx.x & 31;
    const int gw = blockIdx.x * 4 + (threadIdx.x >> 5);  // (b*N + n)
    const int b = gw >> 10, n = gw & 1023;

    // load mask+label row once; addterm = adj>0 ? label : NEGBIG (packed fp16x2)
    __half2 addt[16];
    {
        const size_t rbase = ((size_t)(b << 10) + n) * 1024 + lane * 8;
        const int*   ar = adj   + rbase;
        const float* lr = label + rbase;
        #pragma unroll
        for (int i = 0; i < 4; i++) {
            const int4   a0 = *(const int4*)  (ar + i * 256);
            const int4   a1 = *(const int4*)  (ar + i * 256 + 4);
            const float4 l0 = *(const float4*)(lr + i * 256);
            const float4 l1 = *(const float4*)(lr + i * 256 + 4);
            addt[i*4+0] = __float22half2_rn(make_float2(a0.x > 0 ? l0.x : NEGBIG_,
                                                        a0.y > 0 ? l0.y : NEGBIG_));
            addt[i*4+1] = __float22half2_rn(make_float2(a0.z > 0 ? l0.z : NEGBIG_,
                                                        a0.w > 0 ? l0.w : NEGBIG_));
            addt[i*4+2] = __float22half2_rn(make_float2(a1.x > 0 ? l1.x : NEGBIG_,
                                                        a1.y > 0 ? l1.y : NEGBIG_));
            addt[i*4+3] = __float22half2_rn(make_float2(a1.z > 0 ? l1.z : NEGBIG_,
                                                        a1.w > 0 ? l1.w : NEGBIG_));
        }
    }

    float2 avg[16];
    #pragma unroll
    for (int i = 0; i < 16; i++) avg[i] = make_float2(0.f, 0.f);

    #pragma unroll 1
    for (int h = 0; h < H_; h++) {
        __half* ph = g_AH + (((size_t)(b * H_ + h) << 10) + n) * 1024 + lane * 8;
        float2 f[16];
        #pragma unroll
        for (int i = 0; i < 4; i++) {
            uint4 d = *(const uint4*)(ph + i * 256);
            f[i*4+0] = __half22float2(*(const __half2*)&d.x);
            f[i*4+1] = __half22float2(*(const __half2*)&d.y);
            f[i*4+2] = __half22float2(*(const __half2*)&d.z);
            f[i*4+3] = __half22float2(*(const __half2*)&d.w);
        }
        // apply mask+label (NEGBIG swamps the raw score; exp underflows to 0)
        #pragma unroll
        for (int i = 0; i < 16; i++) {
            const float2 at = __half22float2(addt[i]);
            f[i].x += at.x; f[i].y += at.y;
        }
        float mx = -1e30f;
        #pragma unroll
        for (int i = 0; i < 16; i++) mx = fmaxf(mx, fmaxf(f[i].x, f[i].y));
        #pragma unroll
        for (int o = 16; o; o >>= 1) mx = fmaxf(mx, __shfl_xor_sync(0xffffffffu, mx, o));

        float s = 0.f;
        #pragma unroll
        for (int i = 0; i < 16; i++) {
            f[i].x = __expf(f[i].x - mx);
            f[i].y = __expf(f[i].y - mx);
            s += f[i].x + f[i].y;
        }
        #pragma unroll
        for (int o = 16; o; o >>= 1) s += __shfl_xor_sync(0xffffffffu, s, o);
        const float inv = 1.0f / s;

        #pragma unroll
        for (int i = 0; i < 16; i++) {
            f[i].x *= inv; f[i].y *= inv;
            avg[i].x += f[i].x; avg[i].y += f[i].y;
        }
        #pragma unroll
        for (int i = 0; i < 4; i++) {
            uint4 d;
            *(__half2*)&d.x = __floats2half2_rn(f[i*4+0].x, f[i*4+0].y);
            *(__half2*)&d.y = __floats2half2_rn(f[i*4+1].x, f[i*4+1].y);
            *(__half2*)&d.z = __floats2half2_rn(f[i*4+2].x, f[i*4+2].y);
            *(__half2*)&d.w = __floats2half2_rn(f[i*4+3].x, f[i*4+3].y);
            *(uint4*)(ph + i * 256) = d;
        }
    }
    float* pa = out_att + (((size_t)b << 10) + n) * 1024 + lane * 8;
    #pragma unroll
    for (int i = 0; i < 4; i++) {
        *(float4*)(pa + i * 256) = make_float4(
            avg[i*4+0].x * 0.125f, avg[i*4+0].y * 0.125f,
            avg[i*4+1].x * 0.125f, avg[i*4+1].y * 0.125f);
        *(float4*)(pa + i * 256 + 4) = make_float4(
            avg[i*4+2].x * 0.125f, avg[i*4+2].y * 0.125f,
            avg[i*4+3].x * 0.125f, avg[i*4+3].y * 0.125f);
    }
}

// ----------------------------------------------------------------------------
extern "C" void kernel_launch(void* const* d_in, const int* in_sizes, int n_in,
                              void* d_out, int out_size) {
    const float* obj   = (const float*)d_in[0];
    const float* cross = (const float*)d_in[1];
    const int*   adj   = (const int*)  d_in[2];
    const float* label = (const float*)d_in[3];
    const float* Wq    = (const float*)d_in[4];
    const float* bq    = (const float*)d_in[5];
    const float* Wk    = (const float*)d_in[6];
    const float* bk    = (const float*)d_in[7];
    const float* Wv    = (const float*)d_in[8];
    const float* bv    = (const float*)d_in[9];
    const float* Wo    = (const float*)d_in[10];
    const float* bo    = (const float*)d_in[11];

    float* out     = (float*)d_out;
    float* out_att = out + (size_t)B_ * N_ * F_;

    cudaFuncSetAttribute(tgemm<5>, cudaFuncAttributeMaxDynamicSharedMemorySize, SMEM_BYTES);
    cudaFuncSetAttribute(qkf_kernel, cudaFuncAttributeMaxDynamicSharedMemorySize, SMEM_BYTES);
    cudaFuncSetAttribute(scores_vpt_kernel, cudaFuncAttributeMaxDynamicSharedMemorySize, SMEM_BYTES);

    // ---- fused pre-pass (to_half x5 + transpose + fold_bias) ----
    prep_kernel<<<21504, 256>>>(obj, cross, Wq, Wk, Wo, Wv, bv);

    // ---- Q + K + fold co-scheduled ----
    qkf_kernel<<<dim3(8, 64, 3), 128, SMEM_BYTES>>>(bq, bk);
    // ---- scores (write-only epi) co-scheduled with VpT GEMM ----
    scores_vpt_kernel<<<4608, 128, SMEM_BYTES>>>();
    // ---- warp-per-row softmax(mask+label) + att_avg (round-13 optimum) ----
    softmax_attavg_kernel<<<2048, 128>>>(adj, label, out_att);
    // ---- AV ----
    tgemm<5><<<dim3(1, 8, 64), 128, SMEM_BYTES>>>(bo, out);
}